// round 1
// baseline (speedup 1.0000x reference)
#include <cuda_runtime.h>

#define B_   4
#define SQ_  2048
#define SK_  2048
#define D_   1024
#define H_   16
#define HD_  64
#define SCALE_ 0.125f   // 1/sqrt(64)

// Scratch buffers (static __device__ per allocation rules)
__device__ float g_Q  [(size_t)B_ * SQ_ * D_];        // Q projection  [b, sq, D]
__device__ float g_KV [(size_t)B_ * SK_ * 2 * D_];    // KV projection [b, sk, 2D]
__device__ float g_ctx[(size_t)B_ * SQ_ * D_];        // attention out [b, sq, D]

// ---------------------------------------------------------------------------
// SGEMM + bias: C[M,N] = A[M,K] @ B[K,N] + bias[N]   (all row-major, fp32)
// 128x128 block tile, BK=16, 256 threads, 8x8 per thread.
// ---------------------------------------------------------------------------
__global__ __launch_bounds__(256) void sgemm_bias(
    const float* __restrict__ A, const float* __restrict__ Bm,
    const float* __restrict__ bias, float* __restrict__ C,
    int M, int N, int K)
{
    __shared__ float As[16][128];   // transposed A tile: As[k][m]
    __shared__ float Bs[16][128];   // Bs[k][n]

    const int tid = threadIdx.x;
    const int tx = tid & 15, ty = tid >> 4;
    const int bx = blockIdx.x, by = blockIdx.y;

    const float* Ab = A + (size_t)(by * 128) * K;
    const float* Bb = Bm + bx * 128;

    float acc[8][8];
    #pragma unroll
    for (int i = 0; i < 8; i++)
        #pragma unroll
        for (int j = 0; j < 8; j++) acc[i][j] = 0.f;

    for (int k0 = 0; k0 < K; k0 += 16) {
        #pragma unroll
        for (int it = 0; it < 2; it++) {
            int idx = tid + it * 256;
            // A tile: 128 x 16, float4 per thread
            int r = idx >> 2, c = (idx & 3) << 2;
            float4 va = *(const float4*)(Ab + (size_t)r * K + k0 + c);
            As[c + 0][r] = va.x; As[c + 1][r] = va.y;
            As[c + 2][r] = va.z; As[c + 3][r] = va.w;
            // B tile: 16 x 128, float4 per thread
            int rb = idx >> 5, cb = (idx & 31) << 2;
            *(float4*)&Bs[rb][cb] = *(const float4*)(Bb + (size_t)(k0 + rb) * N + cb);
        }
        __syncthreads();

        #pragma unroll
        for (int kk = 0; kk < 16; kk++) {
            float a[8], b[8];
            #pragma unroll
            for (int i = 0; i < 8; i++) a[i] = As[kk][ty * 8 + i];
            #pragma unroll
            for (int j = 0; j < 8; j++) b[j] = Bs[kk][tx * 8 + j];
            #pragma unroll
            for (int i = 0; i < 8; i++)
                #pragma unroll
                for (int j = 0; j < 8; j++) acc[i][j] += a[i] * b[j];
        }
        __syncthreads();
    }

    #pragma unroll
    for (int i = 0; i < 8; i++) {
        int row = by * 128 + ty * 8 + i;
        #pragma unroll
        for (int j = 0; j < 8; j += 4) {
            int col = bx * 128 + tx * 8 + j;
            float4 v;
            v.x = acc[i][j + 0] + bias[col + 0];
            v.y = acc[i][j + 1] + bias[col + 1];
            v.z = acc[i][j + 2] + bias[col + 2];
            v.w = acc[i][j + 3] + bias[col + 3];
            *(float4*)&C[(size_t)row * N + col] = v;
        }
    }
}

// ---------------------------------------------------------------------------
// Flash attention over fp32: per CTA: 128 queries x one head, K tiles of 64.
// KV layout: [b, sk, 2D] (raw KV-proj output): K head h dim d at col h*64+d,
// V at col 1024 + h*64 + d.
// Thread layout: 16x16; each thread owns 8 q-rows x 4 cols (S) / 4 dims (O).
// Smem (dynamic, padded to 65 to avoid stride-64 bank conflicts):
//   Qs[128][65], Ks[64][65], Vs[64][64], Ps[128][65]  -> 99584 bytes
// ---------------------------------------------------------------------------
#define ATTN_SMEM_BYTES ((128*65 + 64*65 + 64*64 + 128*65) * 4)

__global__ __launch_bounds__(256) void attn_kernel(
    const float* __restrict__ Q, const float* __restrict__ KV,
    float* __restrict__ ctx)
{
    extern __shared__ float sm[];
    float* Qs = sm;                    // [128][65]
    float* Ks = Qs + 128 * 65;         // [64][65]
    float* Vs = Ks + 64 * 65;          // [64][64]
    float* Ps = Vs + 64 * 64;          // [128][65]

    const int tid = threadIdx.x;
    const int tx = tid & 15, ty = tid >> 4;
    const int qt = blockIdx.x, h = blockIdx.y, b = blockIdx.z;
    const int q0 = qt * 128;

    // Load Q tile (coalesced over d)
    for (int idx = tid; idx < 128 * 64; idx += 256) {
        int r = idx >> 6, d = idx & 63;
        Qs[r * 65 + d] = Q[((size_t)(b * SQ_ + q0 + r)) * D_ + h * HD_ + d];
    }

    float m[8], l[8], acc[8][4];
    #pragma unroll
    for (int i = 0; i < 8; i++) {
        m[i] = -1e30f; l[i] = 0.f;
        #pragma unroll
        for (int j = 0; j < 4; j++) acc[i][j] = 0.f;
    }
    __syncthreads();

    const float c2 = SCALE_ * 1.44269504088896340736f;  // scale * log2(e)

    for (int kt = 0; kt < SK_; kt += 64) {
        // Load K and V tiles (coalesced over d; padded K rows)
        for (int idx = tid; idx < 64 * 64; idx += 256) {
            int k = idx >> 6, d = idx & 63;
            size_t base = ((size_t)(b * SK_ + kt + k)) * (2 * D_) + h * HD_ + d;
            Ks[k * 65 + d] = KV[base];
            Vs[k * 64 + d] = KV[base + D_];
        }
        __syncthreads();

        // S = Q @ K^T  (8x4 per thread)
        float s[8][4];
        #pragma unroll
        for (int i = 0; i < 8; i++)
            #pragma unroll
            for (int j = 0; j < 4; j++) s[i][j] = 0.f;

        #pragma unroll 4
        for (int d = 0; d < 64; d++) {
            float kv[4];
            #pragma unroll
            for (int j = 0; j < 4; j++) kv[j] = Ks[(tx * 4 + j) * 65 + d];
            #pragma unroll
            for (int i = 0; i < 8; i++) {
                float qv = Qs[(ty * 8 + i) * 65 + d];
                #pragma unroll
                for (int j = 0; j < 4; j++) s[i][j] += qv * kv[j];
            }
        }

        // Online softmax (row = 16 lanes in the tx dimension; xor-shuffle <16)
        #pragma unroll
        for (int i = 0; i < 8; i++) {
            float tmax = s[i][0];
            #pragma unroll
            for (int j = 1; j < 4; j++) tmax = fmaxf(tmax, s[i][j]);
            #pragma unroll
            for (int o = 1; o < 16; o <<= 1)
                tmax = fmaxf(tmax, __shfl_xor_sync(0xffffffffu, tmax, o));
            float mn  = fmaxf(m[i], tmax);
            float fac = exp2f((m[i] - mn) * c2);
            m[i] = mn;
            float tsum = 0.f;
            #pragma unroll
            for (int j = 0; j < 4; j++) {
                float p = exp2f((s[i][j] - mn) * c2);
                s[i][j] = p; tsum += p;
            }
            #pragma unroll
            for (int o = 1; o < 16; o <<= 1)
                tsum += __shfl_xor_sync(0xffffffffu, tsum, o);
            l[i] = l[i] * fac + tsum;
            #pragma unroll
            for (int j = 0; j < 4; j++) acc[i][j] *= fac;
            #pragma unroll
            for (int j = 0; j < 4; j++)
                Ps[(ty * 8 + i) * 65 + tx * 4 + j] = s[i][j];
        }
        __syncthreads();

        // acc += P @ V  (each thread: 8 rows x dims tx*4..tx*4+3)
        #pragma unroll 4
        for (int j = 0; j < 64; j++) {
            float4 vv = *(const float4*)&Vs[j * 64 + tx * 4];
            #pragma unroll
            for (int i = 0; i < 8; i++) {
                float p = Ps[(ty * 8 + i) * 65 + j];
                acc[i][0] += p * vv.x; acc[i][1] += p * vv.y;
                acc[i][2] += p * vv.z; acc[i][3] += p * vv.w;
            }
        }
        __syncthreads();
    }

    // Normalize and write ctx
    #pragma unroll
    for (int i = 0; i < 8; i++) {
        float inv = 1.f / l[i];
        size_t row = (size_t)(b * SQ_ + q0 + ty * 8 + i);
        float4 v;
        v.x = acc[i][0] * inv; v.y = acc[i][1] * inv;
        v.z = acc[i][2] * inv; v.w = acc[i][3] * inv;
        *(float4*)&ctx[row * D_ + h * HD_ + tx * 4] = v;
    }
}

// ---------------------------------------------------------------------------
extern "C" void kernel_launch(void* const* d_in, const int* in_sizes, int n_in,
                              void* d_out, int out_size)
{
    const float* query     = (const float*)d_in[0];
    const float* key_value = (const float*)d_in[1];
    const float* Wq        = (const float*)d_in[2];
    const float* bq        = (const float*)d_in[3];
    const float* Wkv       = (const float*)d_in[4];
    const float* bkv       = (const float*)d_in[5];
    const float* Wo        = (const float*)d_in[6];
    const float* bo        = (const float*)d_in[7];
    float* out = (float*)d_out;

    float *Qb = nullptr, *KVb = nullptr, *Ctx = nullptr;
    cudaGetSymbolAddress((void**)&Qb,  g_Q);
    cudaGetSymbolAddress((void**)&KVb, g_KV);
    cudaGetSymbolAddress((void**)&Ctx, g_ctx);

    cudaFuncSetAttribute(attn_kernel,
                         cudaFuncAttributeMaxDynamicSharedMemorySize,
                         ATTN_SMEM_BYTES);

    const int M = B_ * SQ_;  // 8192

    // 1) Q projection: [8192,1024] @ [1024,1024] + bq
    sgemm_bias<<<dim3(D_ / 128, M / 128), 256>>>(query, Wq, bq, Qb, M, D_, D_);

    // 2) KV projection: [8192,1024] @ [1024,2048] + bkv
    sgemm_bias<<<dim3(2 * D_ / 128, M / 128), 256>>>(key_value, Wkv, bkv, KVb,
                                                     M, 2 * D_, D_);

    // 3) Attention: grid (SQ/128, H, B)
    attn_kernel<<<dim3(SQ_ / 128, H_, B_), 256, ATTN_SMEM_BYTES>>>(Qb, KVb, Ctx);

    // 4) O projection: [8192,1024] @ [1024,1024] + bo -> out
    sgemm_bias<<<dim3(D_ / 128, M / 128), 256>>>(Ctx, Wo, bo, out, M, D_, D_);
}

// round 3
// speedup vs baseline: 1.2239x; 1.2239x over previous
#include <cuda_runtime.h>
#include <cuda_bf16.h>
#include <cstdint>

#define B_    4
#define SQ_   2048
#define SK_   2048
#define D_    1024
#define H_    16
#define HD_   64
#define SCALE_ 0.125f
#define M_TOT (B_ * SQ_)   // 8192

// ---------------------------------------------------------------------------
// Scratch (__device__ globals per allocation rules)
// ---------------------------------------------------------------------------
__device__ float g_Q  [(size_t)M_TOT * D_];
__device__ float g_KV [(size_t)M_TOT * 2 * D_];
__device__ float g_ctx[(size_t)M_TOT * D_];

__device__ __nv_bfloat16 g_qh[(size_t)M_TOT * D_], g_ql[(size_t)M_TOT * D_];
__device__ __nv_bfloat16 g_kh[(size_t)M_TOT * D_], g_kl[(size_t)M_TOT * D_];
__device__ __nv_bfloat16 g_ch[(size_t)M_TOT * D_], g_cl[(size_t)M_TOT * D_];

__device__ __nv_bfloat16 g_WqTh[D_ * D_],      g_WqTl[D_ * D_];
__device__ __nv_bfloat16 g_WkvTh[2 * D_ * D_], g_WkvTl[2 * D_ * D_];
__device__ __nv_bfloat16 g_WoTh[D_ * D_],      g_WoTl[D_ * D_];

// ---------------------------------------------------------------------------
// Helpers (arch-portable: ldmatrix / mma.sync / cp.async only)
// ---------------------------------------------------------------------------
__device__ __forceinline__ uint32_t smem_u32(const void* p) {
    uint32_t a;
    asm("{ .reg .u64 t; cvta.to.shared.u64 t, %1; cvt.u32.u64 %0, t; }" : "=r"(a) : "l"(p));
    return a;
}

#define SW128(off) ((off) ^ (((off) >> 3) & 0x70))

#define CP16(dst, src) \
    asm volatile("cp.async.cg.shared.global [%0], [%1], 16;" \
                 :: "r"(dst), "l"(src) : "memory")
#define CP_COMMIT() asm volatile("cp.async.commit_group;" ::: "memory")
#define CP_WAIT1()  asm volatile("cp.async.wait_group 1;" ::: "memory")

#define LDSM_X4(r, addr) \
    asm volatile("ldmatrix.sync.aligned.m8n8.x4.shared.b16 {%0,%1,%2,%3}, [%4];" \
                 : "=r"((r)[0]), "=r"((r)[1]), "=r"((r)[2]), "=r"((r)[3]) : "r"(addr))
#define LDSM_X2(r, addr) \
    asm volatile("ldmatrix.sync.aligned.m8n8.x2.shared.b16 {%0,%1}, [%2];" \
                 : "=r"((r)[0]), "=r"((r)[1]) : "r"(addr))

#define MMA16816(c, a, b) \
    asm volatile("mma.sync.aligned.m16n8k16.row.col.f32.bf16.bf16.f32 " \
                 "{%0,%1,%2,%3}, {%4,%5,%6,%7}, {%8,%9}, {%0,%1,%2,%3};" \
                 : "+f"((c)[0]), "+f"((c)[1]), "+f"((c)[2]), "+f"((c)[3]) \
                 : "r"((a)[0]), "r"((a)[1]), "r"((a)[2]), "r"((a)[3]), \
                   "r"((b)[0]), "r"((b)[1]))

// ---------------------------------------------------------------------------
// Prep: fp32 -> bf16 hi/lo split (row-major activations)
// ---------------------------------------------------------------------------
__global__ void prep_act(const float* __restrict__ X,
                         __nv_bfloat16* __restrict__ Xh,
                         __nv_bfloat16* __restrict__ Xl, int n4) {
    int i = blockIdx.x * blockDim.x + threadIdx.x;
    int stride = gridDim.x * blockDim.x;
    for (; i < n4; i += stride) {
        float4 v = ((const float4*)X)[i];
        __nv_bfloat16 h0 = __float2bfloat16_rn(v.x);
        __nv_bfloat16 h1 = __float2bfloat16_rn(v.y);
        __nv_bfloat16 h2 = __float2bfloat16_rn(v.z);
        __nv_bfloat16 h3 = __float2bfloat16_rn(v.w);
        __nv_bfloat162 ph0, ph1, pl0, pl1;
        ph0.x = h0; ph0.y = h1; ph1.x = h2; ph1.y = h3;
        pl0.x = __float2bfloat16_rn(v.x - __bfloat162float(h0));
        pl0.y = __float2bfloat16_rn(v.y - __bfloat162float(h1));
        pl1.x = __float2bfloat16_rn(v.z - __bfloat162float(h2));
        pl1.y = __float2bfloat16_rn(v.w - __bfloat162float(h3));
        ((__nv_bfloat162*)Xh)[i * 2 + 0] = ph0;
        ((__nv_bfloat162*)Xh)[i * 2 + 1] = ph1;
        ((__nv_bfloat162*)Xl)[i * 2 + 0] = pl0;
        ((__nv_bfloat162*)Xl)[i * 2 + 1] = pl1;
    }
}

// W[K][N] fp32 -> WT[N][K] bf16 hi/lo (transpose + split)
__global__ void prep_wT(const float* __restrict__ W,
                        __nv_bfloat16* __restrict__ Th,
                        __nv_bfloat16* __restrict__ Tl, int Kd, int Nd) {
    __shared__ float t[32][33];
    int n  = blockIdx.x * 32 + threadIdx.x;
    int k0 = blockIdx.y * 32;
    for (int i = threadIdx.y; i < 32; i += 8)
        t[i][threadIdx.x] = W[(size_t)(k0 + i) * Nd + n];
    __syncthreads();
    int nn = blockIdx.x * 32;
    for (int i = threadIdx.y; i < 32; i += 8) {
        float v = t[threadIdx.x][i];
        __nv_bfloat16 h = __float2bfloat16_rn(v);
        Th[(size_t)(nn + i) * Kd + k0 + threadIdx.x] = h;
        Tl[(size_t)(nn + i) * Kd + k0 + threadIdx.x] =
            __float2bfloat16_rn(v - __bfloat162float(h));
    }
}

// ---------------------------------------------------------------------------
// Tensor-core GEMM (mma.sync bf16 3-term split):
//   C[M,N] = (Ah+Al)[M,K] @ (Bh+Bl)[N,K]^T + bias
// CTA 128x128, BK=32, 3-stage cp.async pipeline.
// Smem row layout: 128B/row = [ hi k0..31 | lo k0..31 ], SW128 swizzle.
// ---------------------------------------------------------------------------
#define BK      32
#define STAGES  3
#define STAGE_BYTES 32768                      // A tile 16KB + B tile 16KB
#define GEMM_SMEM (1024 + STAGES * STAGE_BYTES)

__global__ __launch_bounds__(256, 2) void gemm_mma(
    const __nv_bfloat16* __restrict__ Ah, const __nv_bfloat16* __restrict__ Al,
    const __nv_bfloat16* __restrict__ Bh, const __nv_bfloat16* __restrict__ Bl,
    const float* __restrict__ bias, float* __restrict__ C, int N, int K)
{
    extern __shared__ char smraw[];
    const uint32_t raw32  = smem_u32(smraw);
    const uint32_t heap32 = (raw32 + 1023) & ~1023u;

    const int tid  = threadIdx.x;
    const int lane = tid & 31, wid = tid >> 5;
    const int wm0  = (wid & 3) * 32;      // warp m offset (4 warps in m)
    const int wn0  = (wid >> 2) * 64;     // warp n offset (2 warps in n)
    const int m0   = blockIdx.y * 128;
    const int n0   = blockIdx.x * 128;

    // ---- loader: threads 0-127 -> A rows, 128-255 -> B rows ----
    const bool isA = tid < 128;
    const int  lrow = isA ? tid : tid - 128;
    const __nv_bfloat16* gh = isA ? Ah + (size_t)(m0 + lrow) * K
                                  : Bh + (size_t)(n0 + lrow) * K;
    const __nv_bfloat16* gl = isA ? Al + (size_t)(m0 + lrow) * K
                                  : Bl + (size_t)(n0 + lrow) * K;
    const uint32_t dstBase = heap32 + (isA ? 0u : 16384u);
    uint32_t dsw[8];
    #pragma unroll
    for (int seg = 0; seg < 4; seg++) {
        dsw[seg]     = SW128((uint32_t)(lrow * 128 + seg * 16));        // hi
        dsw[4 + seg] = SW128((uint32_t)(lrow * 128 + 64 + seg * 16));   // lo
    }

    float acc[2][8][4];
    #pragma unroll
    for (int mt = 0; mt < 2; mt++)
        #pragma unroll
        for (int nt = 0; nt < 8; nt++)
            #pragma unroll
            for (int r = 0; r < 4; r++) acc[mt][nt][r] = 0.f;

    // ldmatrix lane address components
    const uint32_t aRowOff  = (uint32_t)((wm0 + (lane & 15)) * 128 + ((lane >> 4) << 4));
    const uint32_t bRowOff  = (uint32_t)((wn0 + (lane & 7)) * 128 + (((lane >> 3) & 1) << 4));

    const int steps = K / BK;

    // prologue: stages 0,1
    #pragma unroll
    for (int s = 0; s < 2; s++) {
        #pragma unroll
        for (int seg = 0; seg < 4; seg++) {
            CP16(dstBase + s * STAGE_BYTES + dsw[seg],     gh + s * BK + seg * 8);
            CP16(dstBase + s * STAGE_BYTES + dsw[4 + seg], gl + s * BK + seg * 8);
        }
        CP_COMMIT();
    }

    for (int i = 0; i < steps; i++) {
        CP_WAIT1();
        __syncthreads();

        if (i + 2 < steps) {
            const int s = (i + 2) % STAGES;
            const int k0 = (i + 2) * BK;
            #pragma unroll
            for (int seg = 0; seg < 4; seg++) {
                CP16(dstBase + s * STAGE_BYTES + dsw[seg],     gh + k0 + seg * 8);
                CP16(dstBase + s * STAGE_BYTES + dsw[4 + seg], gl + k0 + seg * 8);
            }
        }
        CP_COMMIT();

        const uint32_t aB = heap32 + (i % STAGES) * STAGE_BYTES;
        const uint32_t bB = aB + 16384;

        #pragma unroll
        for (int kh = 0; kh < 2; kh++) {
            uint32_t afh[2][4], afl[2][4];
            #pragma unroll
            for (int mt = 0; mt < 2; mt++) {
                uint32_t off = aRowOff + (uint32_t)(mt * 16 * 128 + kh * 32);
                LDSM_X4(afh[mt], aB + SW128(off));
                LDSM_X4(afl[mt], aB + SW128(off + 64));
            }
            #pragma unroll
            for (int nt = 0; nt < 8; nt++) {
                uint32_t off = bRowOff + (uint32_t)(nt * 8 * 128 + kh * 32);
                uint32_t bfh[2], bfl[2];
                LDSM_X2(bfh, bB + SW128(off));
                LDSM_X2(bfl, bB + SW128(off + 64));
                #pragma unroll
                for (int mt = 0; mt < 2; mt++) {
                    MMA16816(acc[mt][nt], afh[mt], bfh);
                    MMA16816(acc[mt][nt], afh[mt], bfl);
                    MMA16816(acc[mt][nt], afl[mt], bfh);
                }
            }
        }
    }

    // ---- epilogue: direct stores + bias ----
    const int erow = lane >> 2, ecol = (lane & 3) * 2;
    #pragma unroll
    for (int nt = 0; nt < 8; nt++) {
        int col = n0 + wn0 + nt * 8 + ecol;
        float2 bv = *(const float2*)&bias[col];
        #pragma unroll
        for (int mt = 0; mt < 2; mt++) {
            int row = m0 + wm0 + mt * 16 + erow;
            float2 v0, v1;
            v0.x = acc[mt][nt][0] + bv.x;  v0.y = acc[mt][nt][1] + bv.y;
            v1.x = acc[mt][nt][2] + bv.x;  v1.y = acc[mt][nt][3] + bv.y;
            *(float2*)&C[(size_t)row * N + col]       = v0;
            *(float2*)&C[(size_t)(row + 8) * N + col] = v1;
        }
    }
}

// ---------------------------------------------------------------------------
// Flash attention (fp32) — unchanged (R4 target)
// ---------------------------------------------------------------------------
#define ATTN_SMEM_BYTES ((128*65 + 64*65 + 64*64 + 128*65) * 4)

__global__ __launch_bounds__(256) void attn_kernel(
    const float* __restrict__ Q, const float* __restrict__ KV,
    float* __restrict__ ctx)
{
    extern __shared__ float sm[];
    float* Qs = sm;
    float* Ks = Qs + 128 * 65;
    float* Vs = Ks + 64 * 65;
    float* Ps = Vs + 64 * 64;

    const int tid = threadIdx.x;
    const int tx = tid & 15, ty = tid >> 4;
    const int qt = blockIdx.x, h = blockIdx.y, b = blockIdx.z;
    const int q0 = qt * 128;

    for (int idx = tid; idx < 128 * 64; idx += 256) {
        int r = idx >> 6, d = idx & 63;
        Qs[r * 65 + d] = Q[((size_t)(b * SQ_ + q0 + r)) * D_ + h * HD_ + d];
    }

    float m[8], l[8], acc[8][4];
    #pragma unroll
    for (int i = 0; i < 8; i++) {
        m[i] = -1e30f; l[i] = 0.f;
        #pragma unroll
        for (int j = 0; j < 4; j++) acc[i][j] = 0.f;
    }
    __syncthreads();

    const float c2 = SCALE_ * 1.44269504088896340736f;

    for (int kt = 0; kt < SK_; kt += 64) {
        for (int idx = tid; idx < 64 * 64; idx += 256) {
            int k = idx >> 6, d = idx & 63;
            size_t base = ((size_t)(b * SK_ + kt + k)) * (2 * D_) + h * HD_ + d;
            Ks[k * 65 + d] = KV[base];
            Vs[k * 64 + d] = KV[base + D_];
        }
        __syncthreads();

        float s[8][4];
        #pragma unroll
        for (int i = 0; i < 8; i++)
            #pragma unroll
            for (int j = 0; j < 4; j++) s[i][j] = 0.f;

        #pragma unroll 4
        for (int d = 0; d < 64; d++) {
            float kv[4];
            #pragma unroll
            for (int j = 0; j < 4; j++) kv[j] = Ks[(tx * 4 + j) * 65 + d];
            #pragma unroll
            for (int i = 0; i < 8; i++) {
                float qv = Qs[(ty * 8 + i) * 65 + d];
                #pragma unroll
                for (int j = 0; j < 4; j++) s[i][j] += qv * kv[j];
            }
        }

        #pragma unroll
        for (int i = 0; i < 8; i++) {
            float tmax = s[i][0];
            #pragma unroll
            for (int j = 1; j < 4; j++) tmax = fmaxf(tmax, s[i][j]);
            #pragma unroll
            for (int o = 1; o < 16; o <<= 1)
                tmax = fmaxf(tmax, __shfl_xor_sync(0xffffffffu, tmax, o));
            float mn  = fmaxf(m[i], tmax);
            float fac = exp2f((m[i] - mn) * c2);
            m[i] = mn;
            float tsum = 0.f;
            #pragma unroll
            for (int j = 0; j < 4; j++) {
                float p = exp2f((s[i][j] - mn) * c2);
                s[i][j] = p; tsum += p;
            }
            #pragma unroll
            for (int o = 1; o < 16; o <<= 1)
                tsum += __shfl_xor_sync(0xffffffffu, tsum, o);
            l[i] = l[i] * fac + tsum;
            #pragma unroll
            for (int j = 0; j < 4; j++) acc[i][j] *= fac;
            #pragma unroll
            for (int j = 0; j < 4; j++)
                Ps[(ty * 8 + i) * 65 + tx * 4 + j] = s[i][j];
        }
        __syncthreads();

        #pragma unroll 4
        for (int j = 0; j < 64; j++) {
            float4 vv = *(const float4*)&Vs[j * 64 + tx * 4];
            #pragma unroll
            for (int i = 0; i < 8; i++) {
                float p = Ps[(ty * 8 + i) * 65 + j];
                acc[i][0] += p * vv.x; acc[i][1] += p * vv.y;
                acc[i][2] += p * vv.z; acc[i][3] += p * vv.w;
            }
        }
        __syncthreads();
    }

    #pragma unroll
    for (int i = 0; i < 8; i++) {
        float inv = 1.f / l[i];
        size_t row = (size_t)(b * SQ_ + q0 + ty * 8 + i);
        float4 v;
        v.x = acc[i][0] * inv; v.y = acc[i][1] * inv;
        v.z = acc[i][2] * inv; v.w = acc[i][3] * inv;
        *(float4*)&ctx[row * D_ + h * HD_ + tx * 4] = v;
    }
}

// ---------------------------------------------------------------------------
extern "C" void kernel_launch(void* const* d_in, const int* in_sizes, int n_in,
                              void* d_out, int out_size)
{
    const float* query     = (const float*)d_in[0];
    const float* key_value = (const float*)d_in[1];
    const float* Wq        = (const float*)d_in[2];
    const float* bq        = (const float*)d_in[3];
    const float* Wkv       = (const float*)d_in[4];
    const float* bkv       = (const float*)d_in[5];
    const float* Wo        = (const float*)d_in[6];
    const float* bo        = (const float*)d_in[7];
    float* out = (float*)d_out;

    float *Qb, *KVb, *Ctx;
    __nv_bfloat16 *qh, *ql, *kh, *kl, *ch, *cl;
    __nv_bfloat16 *WqTh, *WqTl, *WkvTh, *WkvTl, *WoTh, *WoTl;
    cudaGetSymbolAddress((void**)&Qb,   g_Q);
    cudaGetSymbolAddress((void**)&KVb,  g_KV);
    cudaGetSymbolAddress((void**)&Ctx,  g_ctx);
    cudaGetSymbolAddress((void**)&qh,   g_qh);   cudaGetSymbolAddress((void**)&ql, g_ql);
    cudaGetSymbolAddress((void**)&kh,   g_kh);   cudaGetSymbolAddress((void**)&kl, g_kl);
    cudaGetSymbolAddress((void**)&ch,   g_ch);   cudaGetSymbolAddress((void**)&cl, g_cl);
    cudaGetSymbolAddress((void**)&WqTh, g_WqTh); cudaGetSymbolAddress((void**)&WqTl, g_WqTl);
    cudaGetSymbolAddress((void**)&WkvTh,g_WkvTh);cudaGetSymbolAddress((void**)&WkvTl,g_WkvTl);
    cudaGetSymbolAddress((void**)&WoTh, g_WoTh); cudaGetSymbolAddress((void**)&WoTl, g_WoTl);

    cudaFuncSetAttribute(gemm_mma, cudaFuncAttributeMaxDynamicSharedMemorySize, GEMM_SMEM);
    cudaFuncSetAttribute(attn_kernel, cudaFuncAttributeMaxDynamicSharedMemorySize, ATTN_SMEM_BYTES);

    // Weight transpose + split -> [N][K] bf16 hi/lo
    prep_wT<<<dim3(D_ / 32,     D_ / 32), dim3(32, 8)>>>(Wq,  WqTh,  WqTl,  D_, D_);
    prep_wT<<<dim3(2 * D_ / 32, D_ / 32), dim3(32, 8)>>>(Wkv, WkvTh, WkvTl, D_, 2 * D_);
    prep_wT<<<dim3(D_ / 32,     D_ / 32), dim3(32, 8)>>>(Wo,  WoTh,  WoTl,  D_, D_);

    // Activation splits
    prep_act<<<2048, 256>>>(query,     qh, ql, M_TOT * D_ / 4);
    prep_act<<<2048, 256>>>(key_value, kh, kl, M_TOT * D_ / 4);

    // Projections on tensor cores (mma.sync bf16 3-term split)
    gemm_mma<<<dim3(D_ / 128,     M_TOT / 128), 256, GEMM_SMEM>>>(
        qh, ql, WqTh, WqTl, bq, Qb, D_, D_);
    gemm_mma<<<dim3(2 * D_ / 128, M_TOT / 128), 256, GEMM_SMEM>>>(
        kh, kl, WkvTh, WkvTl, bkv, KVb, 2 * D_, D_);

    // Attention (fp32)
    attn_kernel<<<dim3(SQ_ / 128, H_, B_), 256, ATTN_SMEM_BYTES>>>(Qb, KVb, Ctx);

    // O projection
    prep_act<<<2048, 256>>>(Ctx, ch, cl, M_TOT * D_ / 4);
    gemm_mma<<<dim3(D_ / 128, M_TOT / 128), 256, GEMM_SMEM>>>(
        ch, cl, WoTh, WoTl, bo, out, D_, D_);
}

// round 5
// speedup vs baseline: 2.0199x; 1.6504x over previous
#include <cuda_runtime.h>
#include <cuda_bf16.h>
#include <cstdint>

#define B_    4
#define SQ_   2048
#define SK_   2048
#define D_    1024
#define H_    16
#define HD_   64
#define SCALE_ 0.125f
#define M_TOT (B_ * SQ_)   // 8192

// ---------------------------------------------------------------------------
// Scratch (__device__ globals per allocation rules)
// ---------------------------------------------------------------------------
__device__ float g_Q  [(size_t)M_TOT * D_];
__device__ float g_KV [(size_t)M_TOT * 2 * D_];
__device__ float g_ctx[(size_t)M_TOT * D_];

__device__ __nv_bfloat16 g_qh[(size_t)M_TOT * D_], g_ql[(size_t)M_TOT * D_];
__device__ __nv_bfloat16 g_kh[(size_t)M_TOT * D_], g_kl[(size_t)M_TOT * D_];
__device__ __nv_bfloat16 g_ch[(size_t)M_TOT * D_], g_cl[(size_t)M_TOT * D_];

__device__ __nv_bfloat16 g_WqTh[D_ * D_],      g_WqTl[D_ * D_];
__device__ __nv_bfloat16 g_WkvTh[2 * D_ * D_], g_WkvTl[2 * D_ * D_];
__device__ __nv_bfloat16 g_WoTh[D_ * D_],      g_WoTl[D_ * D_];

// Per-head split arrays for attention: [b*H + h][seq][64]
__device__ __nv_bfloat16 g_Qh2[(size_t)M_TOT * D_], g_Ql2[(size_t)M_TOT * D_];
__device__ __nv_bfloat16 g_Kh2[(size_t)M_TOT * D_], g_Kl2[(size_t)M_TOT * D_];
__device__ __nv_bfloat16 g_Vh2[(size_t)M_TOT * D_], g_Vl2[(size_t)M_TOT * D_];

// ---------------------------------------------------------------------------
// Helpers (arch-portable: ldmatrix / mma.sync / cp.async only)
// ---------------------------------------------------------------------------
__device__ __forceinline__ uint32_t smem_u32(const void* p) {
    uint32_t a;
    asm("{ .reg .u64 t; cvta.to.shared.u64 t, %1; cvt.u32.u64 %0, t; }" : "=r"(a) : "l"(p));
    return a;
}

#define SW128(off) ((off) ^ (((off) >> 3) & 0x70))

#define CP16(dst, src) \
    asm volatile("cp.async.cg.shared.global [%0], [%1], 16;" \
                 :: "r"(dst), "l"(src) : "memory")
#define CP_COMMIT() asm volatile("cp.async.commit_group;" ::: "memory")
#define CP_WAIT1()  asm volatile("cp.async.wait_group 1;" ::: "memory")

#define LDSM_X4(r, addr) \
    asm volatile("ldmatrix.sync.aligned.m8n8.x4.shared.b16 {%0,%1,%2,%3}, [%4];" \
                 : "=r"((r)[0]), "=r"((r)[1]), "=r"((r)[2]), "=r"((r)[3]) : "r"(addr))
#define LDSM_X4_T(r, addr) \
    asm volatile("ldmatrix.sync.aligned.m8n8.x4.trans.shared.b16 {%0,%1,%2,%3}, [%4];" \
                 : "=r"((r)[0]), "=r"((r)[1]), "=r"((r)[2]), "=r"((r)[3]) : "r"(addr))
#define LDSM_X2(r, addr) \
    asm volatile("ldmatrix.sync.aligned.m8n8.x2.shared.b16 {%0,%1}, [%2];" \
                 : "=r"((r)[0]), "=r"((r)[1]) : "r"(addr))

#define MMA16816(c, a, b) \
    asm volatile("mma.sync.aligned.m16n8k16.row.col.f32.bf16.bf16.f32 " \
                 "{%0,%1,%2,%3}, {%4,%5,%6,%7}, {%8,%9}, {%0,%1,%2,%3};" \
                 : "+f"((c)[0]), "+f"((c)[1]), "+f"((c)[2]), "+f"((c)[3]) \
                 : "r"((a)[0]), "r"((a)[1]), "r"((a)[2]), "r"((a)[3]), \
                   "r"((b)[0]), "r"((b)[1]))

__device__ __forceinline__ void split2(float x, float y, uint32_t& hi, uint32_t& lo) {
    __nv_bfloat162 h = __floats2bfloat162_rn(x, y);
    float hx = __bfloat162float(h.x), hy = __bfloat162float(h.y);
    __nv_bfloat162 l = __floats2bfloat162_rn(x - hx, y - hy);
    hi = reinterpret_cast<uint32_t&>(h);
    lo = reinterpret_cast<uint32_t&>(l);
}

// ---------------------------------------------------------------------------
// Prep kernels
// ---------------------------------------------------------------------------
__global__ void prep_act(const float* __restrict__ X,
                         __nv_bfloat16* __restrict__ Xh,
                         __nv_bfloat16* __restrict__ Xl, int n4) {
    int i = blockIdx.x * blockDim.x + threadIdx.x;
    int stride = gridDim.x * blockDim.x;
    for (; i < n4; i += stride) {
        float4 v = ((const float4*)X)[i];
        uint32_t h0, l0, h1, l1;
        split2(v.x, v.y, h0, l0);
        split2(v.z, v.w, h1, l1);
        ((uint32_t*)Xh)[i * 2 + 0] = h0;
        ((uint32_t*)Xh)[i * 2 + 1] = h1;
        ((uint32_t*)Xl)[i * 2 + 0] = l0;
        ((uint32_t*)Xl)[i * 2 + 1] = l1;
    }
}

__global__ void prep_wT(const float* __restrict__ W,
                        __nv_bfloat16* __restrict__ Th,
                        __nv_bfloat16* __restrict__ Tl, int Kd, int Nd) {
    __shared__ float t[32][33];
    int n  = blockIdx.x * 32 + threadIdx.x;
    int k0 = blockIdx.y * 32;
    for (int i = threadIdx.y; i < 32; i += 8)
        t[i][threadIdx.x] = W[(size_t)(k0 + i) * Nd + n];
    __syncthreads();
    int nn = blockIdx.x * 32;
    for (int i = threadIdx.y; i < 32; i += 8) {
        float v = t[threadIdx.x][i];
        __nv_bfloat16 h = __float2bfloat16_rn(v);
        Th[(size_t)(nn + i) * Kd + k0 + threadIdx.x] = h;
        Tl[(size_t)(nn + i) * Kd + k0 + threadIdx.x] =
            __float2bfloat16_rn(v - __bfloat162float(h));
    }
}

// Rearrange+split Q proj and KV proj into per-head bf16 hi/lo arrays.
__global__ void prep_split_qkv(const float* __restrict__ Q, const float* __restrict__ KV,
                               __nv_bfloat16* __restrict__ Qh, __nv_bfloat16* __restrict__ Ql,
                               __nv_bfloat16* __restrict__ Kh, __nv_bfloat16* __restrict__ Kl,
                               __nv_bfloat16* __restrict__ Vh, __nv_bfloat16* __restrict__ Vl) {
    const int total = M_TOT * D_ / 2;   // 4M
    int idx = blockIdx.x * blockDim.x + threadIdx.x;
    int stride = gridDim.x * blockDim.x;
    for (; idx < total; idx += stride) {
        int d2 = idx & 31;
        int s  = (idx >> 5) & 2047;
        int bh = idx >> 16;
        int h = bh & 15, b = bh >> 4;
        size_t qsrc = ((size_t)(b * SQ_ + s)) * D_ + h * 64 + d2 * 2;
        size_t ksrc = ((size_t)(b * SK_ + s)) * (2 * D_) + h * 64 + d2 * 2;
        float2 qv = *(const float2*)(Q + qsrc);
        float2 kv = *(const float2*)(KV + ksrc);
        float2 vv = *(const float2*)(KV + ksrc + D_);
        uint32_t hi, lo;
        split2(qv.x, qv.y, hi, lo);
        ((uint32_t*)Qh)[idx] = hi; ((uint32_t*)Ql)[idx] = lo;
        split2(kv.x, kv.y, hi, lo);
        ((uint32_t*)Kh)[idx] = hi; ((uint32_t*)Kl)[idx] = lo;
        split2(vv.x, vv.y, hi, lo);
        ((uint32_t*)Vh)[idx] = hi; ((uint32_t*)Vl)[idx] = lo;
    }
}

// ---------------------------------------------------------------------------
// Tensor-core GEMM (validated in R3)
// ---------------------------------------------------------------------------
#define BK      32
#define STAGES  3
#define STAGE_BYTES 32768
#define GEMM_SMEM (1024 + STAGES * STAGE_BYTES)

__global__ __launch_bounds__(256, 2) void gemm_mma(
    const __nv_bfloat16* __restrict__ Ah, const __nv_bfloat16* __restrict__ Al,
    const __nv_bfloat16* __restrict__ Bh, const __nv_bfloat16* __restrict__ Bl,
    const float* __restrict__ bias, float* __restrict__ C, int N, int K)
{
    extern __shared__ char smraw[];
    const uint32_t raw32  = smem_u32(smraw);
    const uint32_t heap32 = (raw32 + 1023) & ~1023u;

    const int tid  = threadIdx.x;
    const int lane = tid & 31, wid = tid >> 5;
    const int wm0  = (wid & 3) * 32;
    const int wn0  = (wid >> 2) * 64;
    const int m0   = blockIdx.y * 128;
    const int n0   = blockIdx.x * 128;

    const bool isA = tid < 128;
    const int  lrow = isA ? tid : tid - 128;
    const __nv_bfloat16* gh = isA ? Ah + (size_t)(m0 + lrow) * K
                                  : Bh + (size_t)(n0 + lrow) * K;
    const __nv_bfloat16* gl = isA ? Al + (size_t)(m0 + lrow) * K
                                  : Bl + (size_t)(n0 + lrow) * K;
    const uint32_t dstBase = heap32 + (isA ? 0u : 16384u);
    uint32_t dsw[8];
    #pragma unroll
    for (int seg = 0; seg < 4; seg++) {
        dsw[seg]     = SW128((uint32_t)(lrow * 128 + seg * 16));
        dsw[4 + seg] = SW128((uint32_t)(lrow * 128 + 64 + seg * 16));
    }

    float acc[2][8][4];
    #pragma unroll
    for (int mt = 0; mt < 2; mt++)
        #pragma unroll
        for (int nt = 0; nt < 8; nt++)
            #pragma unroll
            for (int r = 0; r < 4; r++) acc[mt][nt][r] = 0.f;

    const uint32_t aRowOff = (uint32_t)((wm0 + (lane & 15)) * 128 + ((lane >> 4) << 4));
    const uint32_t bRowOff = (uint32_t)((wn0 + (lane & 7)) * 128 + (((lane >> 3) & 1) << 4));

    const int steps = K / BK;

    #pragma unroll
    for (int s = 0; s < 2; s++) {
        #pragma unroll
        for (int seg = 0; seg < 4; seg++) {
            CP16(dstBase + s * STAGE_BYTES + dsw[seg],     gh + s * BK + seg * 8);
            CP16(dstBase + s * STAGE_BYTES + dsw[4 + seg], gl + s * BK + seg * 8);
        }
        CP_COMMIT();
    }

    for (int i = 0; i < steps; i++) {
        CP_WAIT1();
        __syncthreads();

        if (i + 2 < steps) {
            const int s = (i + 2) % STAGES;
            const int k0 = (i + 2) * BK;
            #pragma unroll
            for (int seg = 0; seg < 4; seg++) {
                CP16(dstBase + s * STAGE_BYTES + dsw[seg],     gh + k0 + seg * 8);
                CP16(dstBase + s * STAGE_BYTES + dsw[4 + seg], gl + k0 + seg * 8);
            }
        }
        CP_COMMIT();

        const uint32_t aB = heap32 + (i % STAGES) * STAGE_BYTES;
        const uint32_t bB = aB + 16384;

        #pragma unroll
        for (int kh = 0; kh < 2; kh++) {
            uint32_t afh[2][4], afl[2][4];
            #pragma unroll
            for (int mt = 0; mt < 2; mt++) {
                uint32_t off = aRowOff + (uint32_t)(mt * 16 * 128 + kh * 32);
                LDSM_X4(afh[mt], aB + SW128(off));
                LDSM_X4(afl[mt], aB + SW128(off + 64));
            }
            #pragma unroll
            for (int nt = 0; nt < 8; nt++) {
                uint32_t off = bRowOff + (uint32_t)(nt * 8 * 128 + kh * 32);
                uint32_t bfh[2], bfl[2];
                LDSM_X2(bfh, bB + SW128(off));
                LDSM_X2(bfl, bB + SW128(off + 64));
                #pragma unroll
                for (int mt = 0; mt < 2; mt++) {
                    MMA16816(acc[mt][nt], afh[mt], bfh);
                    MMA16816(acc[mt][nt], afh[mt], bfl);
                    MMA16816(acc[mt][nt], afl[mt], bfh);
                }
            }
        }
    }

    const int erow = lane >> 2, ecol = (lane & 3) * 2;
    #pragma unroll
    for (int nt = 0; nt < 8; nt++) {
        int col = n0 + wn0 + nt * 8 + ecol;
        float2 bv = *(const float2*)&bias[col];
        #pragma unroll
        for (int mt = 0; mt < 2; mt++) {
            int row = m0 + wm0 + mt * 16 + erow;
            float2 v0, v1;
            v0.x = acc[mt][nt][0] + bv.x;  v0.y = acc[mt][nt][1] + bv.y;
            v1.x = acc[mt][nt][2] + bv.x;  v1.y = acc[mt][nt][3] + bv.y;
            *(float2*)&C[(size_t)row * N + col]       = v0;
            *(float2*)&C[(size_t)(row + 8) * N + col] = v1;
        }
    }
}

// ---------------------------------------------------------------------------
// Tensor-core flash attention (bf16 3-term split, mma.sync)
// CTA: 128 q-rows x 1 head. 8 warps x 16 rows. Key tile 64. 2-stage cp.async.
// ---------------------------------------------------------------------------
#define ATTN_SMEM (98304 + 1024)

__global__ __launch_bounds__(256, 2) void attn_tc(
    const __nv_bfloat16* __restrict__ Qh2, const __nv_bfloat16* __restrict__ Ql2,
    const __nv_bfloat16* __restrict__ Kh2, const __nv_bfloat16* __restrict__ Kl2,
    const __nv_bfloat16* __restrict__ Vh2, const __nv_bfloat16* __restrict__ Vl2,
    float* __restrict__ ctx)
{
    extern __shared__ char smraw[];
    const uint32_t raw32  = smem_u32(smraw);
    const uint32_t heap32 = (raw32 + 1023) & ~1023u;

    const int tid  = threadIdx.x;
    const int lane = tid & 31, wid = tid >> 5;
    const int q0 = blockIdx.x * 128;
    const int h  = blockIdx.y, b = blockIdx.z;
    const int bh = b * H_ + h;
    const size_t headQ = (size_t)bh * SQ_ * 64;
    const size_t headK = (size_t)bh * SK_ * 64;

    const uint32_t QH = heap32, QL = heap32 + 16384;
    #define STG(s) (heap32 + 32768u + (uint32_t)(s) * 32768u)  // KH,KL,VH,VL @ +0,8K,16K,24K

    // Q load (once)
    {
        const int arr = tid >> 7, r = tid & 127;
        const __nv_bfloat16* src = (arr ? Ql2 : Qh2) + headQ + (size_t)(q0 + r) * 64;
        const uint32_t dst = heap32 + (uint32_t)arr * 16384u;
        #pragma unroll
        for (int seg = 0; seg < 8; seg++)
            CP16(dst + SW128((uint32_t)(r * 128 + seg * 16)), src + seg * 8);
    }
    // stage loader
    const int larr = tid >> 6, lrow = tid & 63;
    const __nv_bfloat16* lsrc0 =
        (larr == 0 ? Kh2 : larr == 1 ? Kl2 : larr == 2 ? Vh2 : Vl2) + headK + (size_t)lrow * 64;
    uint32_t lsw[8];
    #pragma unroll
    for (int seg = 0; seg < 8; seg++)
        lsw[seg] = (uint32_t)larr * 8192u + SW128((uint32_t)(lrow * 128 + seg * 16));

    #pragma unroll
    for (int seg = 0; seg < 8; seg++)
        CP16(STG(0) + lsw[seg], lsrc0 + seg * 8);
    CP_COMMIT();

    float oacc[8][4];
    #pragma unroll
    for (int nt = 0; nt < 8; nt++)
        #pragma unroll
        for (int r = 0; r < 4; r++) oacc[nt][r] = 0.f;
    float mrow[2] = {-1e30f, -1e30f}, lrowsum[2] = {0.f, 0.f};

    const float c2 = SCALE_ * 1.44269504088896340736f;
    const int wm = wid * 16;
    const uint32_t aOff = (uint32_t)((wm + (lane & 15)) * 128 + ((lane >> 4) << 4));
    const uint32_t kOff = (uint32_t)((lane & 15) * 128 + ((lane >> 4) << 4));
    const uint32_t vOff = (uint32_t)((lane & 15) * 128 + ((lane >> 4) << 4));

    const int iters = SK_ / 64;
    for (int i = 0; i < iters; i++) {
        __syncthreads();
        if (i + 1 < iters) {
            const __nv_bfloat16* src = lsrc0 + (size_t)(i + 1) * 64 * 64;
            const uint32_t stg = STG((i + 1) & 1);
            #pragma unroll
            for (int seg = 0; seg < 8; seg++)
                CP16(stg + lsw[seg], src + seg * 8);
        }
        CP_COMMIT();
        CP_WAIT1();
        __syncthreads();

        const uint32_t KH = STG(i & 1), KL = KH + 8192, VH = KH + 16384, VL = KH + 24576;

        // S = (Qh+Ql)(Kh+Kl)^T, 3-term
        float sacc[8][4];
        #pragma unroll
        for (int nt = 0; nt < 8; nt++)
            #pragma unroll
            for (int r = 0; r < 4; r++) sacc[nt][r] = 0.f;

        #pragma unroll
        for (int kc = 0; kc < 4; kc++) {
            uint32_t afh[4], afl[4];
            LDSM_X4(afh, QH + SW128(aOff + kc * 32));
            LDSM_X4(afl, QL + SW128(aOff + kc * 32));
            #pragma unroll
            for (int ntp = 0; ntp < 4; ntp++) {
                uint32_t b4h[4], b4l[4];
                uint32_t off = kOff + (uint32_t)(ntp * 2048 + kc * 32);
                LDSM_X4(b4h, KH + SW128(off));
                LDSM_X4(b4l, KL + SW128(off));
                uint32_t bh0[2] = {b4h[0], b4h[2]}, bh1[2] = {b4h[1], b4h[3]};
                uint32_t bl0[2] = {b4l[0], b4l[2]}, bl1[2] = {b4l[1], b4l[3]};
                MMA16816(sacc[2 * ntp],     afh, bh0);
                MMA16816(sacc[2 * ntp],     afh, bl0);
                MMA16816(sacc[2 * ntp],     afl, bh0);
                MMA16816(sacc[2 * ntp + 1], afh, bh1);
                MMA16816(sacc[2 * ntp + 1], afh, bl1);
                MMA16816(sacc[2 * ntp + 1], afl, bh1);
            }
        }

        // online softmax
        float fac[2];
        #pragma unroll
        for (int j = 0; j < 2; j++) {
            float tmax = -1e30f;
            #pragma unroll
            for (int nt = 0; nt < 8; nt++)
                tmax = fmaxf(tmax, fmaxf(sacc[nt][2 * j], sacc[nt][2 * j + 1]));
            tmax = fmaxf(tmax, __shfl_xor_sync(0xffffffffu, tmax, 1));
            tmax = fmaxf(tmax, __shfl_xor_sync(0xffffffffu, tmax, 2));
            float mn = fmaxf(mrow[j], tmax);
            fac[j] = exp2f((mrow[j] - mn) * c2);
            mrow[j] = mn;
            float tsum = 0.f;
            #pragma unroll
            for (int nt = 0; nt < 8; nt++) {
                float p0 = exp2f((sacc[nt][2 * j]     - mn) * c2);
                float p1 = exp2f((sacc[nt][2 * j + 1] - mn) * c2);
                sacc[nt][2 * j] = p0; sacc[nt][2 * j + 1] = p1;
                tsum += p0 + p1;
            }
            tsum += __shfl_xor_sync(0xffffffffu, tsum, 1);
            tsum += __shfl_xor_sync(0xffffffffu, tsum, 2);
            lrowsum[j] = lrowsum[j] * fac[j] + tsum;
            #pragma unroll
            for (int nt = 0; nt < 8; nt++) {
                oacc[nt][2 * j]     *= fac[j];
                oacc[nt][2 * j + 1] *= fac[j];
            }
        }

        // O += (Ph+Pl)(Vh+Vl), 3-term; P from registers
        #pragma unroll
        for (int kc = 0; kc < 4; kc++) {
            uint32_t ah[4], al[4];
            split2(sacc[2 * kc][0],     sacc[2 * kc][1],     ah[0], al[0]);
            split2(sacc[2 * kc][2],     sacc[2 * kc][3],     ah[1], al[1]);
            split2(sacc[2 * kc + 1][0], sacc[2 * kc + 1][1], ah[2], al[2]);
            split2(sacc[2 * kc + 1][2], sacc[2 * kc + 1][3], ah[3], al[3]);
            #pragma unroll
            for (int ntp = 0; ntp < 4; ntp++) {
                uint32_t v4h[4], v4l[4];
                uint32_t off = vOff + (uint32_t)(kc * 2048 + ntp * 32);
                LDSM_X4_T(v4h, VH + SW128(off));
                LDSM_X4_T(v4l, VL + SW128(off));
                uint32_t bh0[2] = {v4h[0], v4h[1]}, bh1[2] = {v4h[2], v4h[3]};
                uint32_t bl0[2] = {v4l[0], v4l[1]}, bl1[2] = {v4l[2], v4l[3]};
                MMA16816(oacc[2 * ntp],     ah, bh0);
                MMA16816(oacc[2 * ntp],     ah, bl0);
                MMA16816(oacc[2 * ntp],     al, bh0);
                MMA16816(oacc[2 * ntp + 1], ah, bh1);
                MMA16816(oacc[2 * ntp + 1], ah, bl1);
                MMA16816(oacc[2 * ntp + 1], al, bh1);
            }
        }
    }

    // normalize + store ctx [b, sq, D]
    const float inv0 = 1.f / lrowsum[0], inv1 = 1.f / lrowsum[1];
    const int r0 = q0 + wm + (lane >> 2);
    const int col0 = h * 64 + (lane & 3) * 2;
    #pragma unroll
    for (int nt = 0; nt < 8; nt++) {
        int col = col0 + nt * 8;
        float2 v0, v1;
        v0.x = oacc[nt][0] * inv0;  v0.y = oacc[nt][1] * inv0;
        v1.x = oacc[nt][2] * inv1;  v1.y = oacc[nt][3] * inv1;
        *(float2*)&ctx[((size_t)(b * SQ_ + r0))     * D_ + col] = v0;
        *(float2*)&ctx[((size_t)(b * SQ_ + r0 + 8)) * D_ + col] = v1;
    }
}

// ---------------------------------------------------------------------------
extern "C" void kernel_launch(void* const* d_in, const int* in_sizes, int n_in,
                              void* d_out, int out_size)
{
    const float* query     = (const float*)d_in[0];
    const float* key_value = (const float*)d_in[1];
    const float* Wq        = (const float*)d_in[2];
    const float* bq        = (const float*)d_in[3];
    const float* Wkv       = (const float*)d_in[4];
    const float* bkv       = (const float*)d_in[5];
    const float* Wo        = (const float*)d_in[6];
    const float* bo        = (const float*)d_in[7];
    float* out = (float*)d_out;

    float *Qb, *KVb, *Ctx;
    __nv_bfloat16 *qh, *ql, *kh, *kl, *ch, *cl;
    __nv_bfloat16 *WqTh, *WqTl, *WkvTh, *WkvTl, *WoTh, *WoTl;
    __nv_bfloat16 *Qh2, *Ql2, *Kh2, *Kl2, *Vh2, *Vl2;
    cudaGetSymbolAddress((void**)&Qb,   g_Q);
    cudaGetSymbolAddress((void**)&KVb,  g_KV);
    cudaGetSymbolAddress((void**)&Ctx,  g_ctx);
    cudaGetSymbolAddress((void**)&qh,   g_qh);   cudaGetSymbolAddress((void**)&ql, g_ql);
    cudaGetSymbolAddress((void**)&kh,   g_kh);   cudaGetSymbolAddress((void**)&kl, g_kl);
    cudaGetSymbolAddress((void**)&ch,   g_ch);   cudaGetSymbolAddress((void**)&cl, g_cl);
    cudaGetSymbolAddress((void**)&WqTh, g_WqTh); cudaGetSymbolAddress((void**)&WqTl, g_WqTl);
    cudaGetSymbolAddress((void**)&WkvTh,g_WkvTh);cudaGetSymbolAddress((void**)&WkvTl,g_WkvTl);
    cudaGetSymbolAddress((void**)&WoTh, g_WoTh); cudaGetSymbolAddress((void**)&WoTl, g_WoTl);
    cudaGetSymbolAddress((void**)&Qh2,  g_Qh2);  cudaGetSymbolAddress((void**)&Ql2, g_Ql2);
    cudaGetSymbolAddress((void**)&Kh2,  g_Kh2);  cudaGetSymbolAddress((void**)&Kl2, g_Kl2);
    cudaGetSymbolAddress((void**)&Vh2,  g_Vh2);  cudaGetSymbolAddress((void**)&Vl2, g_Vl2);

    cudaFuncSetAttribute(gemm_mma, cudaFuncAttributeMaxDynamicSharedMemorySize, GEMM_SMEM);
    cudaFuncSetAttribute(attn_tc,  cudaFuncAttributeMaxDynamicSharedMemorySize, ATTN_SMEM);

    // Weight transpose + split
    prep_wT<<<dim3(D_ / 32,     D_ / 32), dim3(32, 8)>>>(Wq,  WqTh,  WqTl,  D_, D_);
    prep_wT<<<dim3(2 * D_ / 32, D_ / 32), dim3(32, 8)>>>(Wkv, WkvTh, WkvTl, D_, 2 * D_);
    prep_wT<<<dim3(D_ / 32,     D_ / 32), dim3(32, 8)>>>(Wo,  WoTh,  WoTl,  D_, D_);

    // Activation splits for projections
    prep_act<<<2048, 256>>>(query,     qh, ql, M_TOT * D_ / 4);
    prep_act<<<2048, 256>>>(key_value, kh, kl, M_TOT * D_ / 4);

    // Q / KV projections (tensor cores)
    gemm_mma<<<dim3(D_ / 128,     M_TOT / 128), 256, GEMM_SMEM>>>(
        qh, ql, WqTh, WqTl, bq, Qb, D_, D_);
    gemm_mma<<<dim3(2 * D_ / 128, M_TOT / 128), 256, GEMM_SMEM>>>(
        kh, kl, WkvTh, WkvTl, bkv, KVb, 2 * D_, D_);

    // Split + per-head rearrange for attention
    prep_split_qkv<<<2048, 256>>>(Qb, KVb, Qh2, Ql2, Kh2, Kl2, Vh2, Vl2);

    // Attention (tensor cores)
    attn_tc<<<dim3(SQ_ / 128, H_, B_), 256, ATTN_SMEM>>>(
        Qh2, Ql2, Kh2, Kl2, Vh2, Vl2, Ctx);

    // O projection
    prep_act<<<2048, 256>>>(Ctx, ch, cl, M_TOT * D_ / 4);
    gemm_mma<<<dim3(D_ / 128, M_TOT / 128), 256, GEMM_SMEM>>>(
        ch, cl, WoTh, WoTl, bo, out, D_, D_);
}